// round 16
// baseline (speedup 1.0000x reference)
#include <cuda_runtime.h>
#include <cuda_bf16.h>
#include <cuda_fp16.h>
#include <math.h>
#include <stdint.h>

#define BATCH 8
#define C 512
#define NPIX 4096
#define HEADS 8
#define CH 64
#define QKV_M 1536
#define NSPLIT 16
#define SQRT_C 22.627416997969522f
#define LOG2E 1.4426950408889634f

// GEMM tiling: CTA 128x128, BK=32, 512 threads, warp 32x32, 2 CTA/SM, 4 stages
#define BM 128
#define BN 128
#define KST 40
#define GTHREADS 512
#define STAGE_BYTES (2 * BM * KST * 2)
#define NSTAGE 4
#define GEMM_SMEM (NSTAGE * STAGE_BYTES)   // 81920

#define KVPAD 264
#define KV_SMEM (2 * 64 * KVPAD * 2)

// ---------------- device scratch ----------------
__device__ __half g_wh[QKV_M * C];
__device__ __half g_fh[C * C];
__device__ __half g_xh[(size_t)BATCH * NPIX * C];
__device__ __half g_qkvh[(size_t)BATCH * QKV_M * NPIX];
__device__ float g_part[(size_t)NSPLIT * BATCH * HEADS * CH * CH];
__device__ float g_spart[(size_t)NSPLIT * BATCH * HEADS * CH];
__device__ __half g_attnh[BATCH * HEADS * CH * CH];
__device__ __half g_oh[(size_t)BATCH * NPIX * C];
__device__ __half g_ffnh[(size_t)BATCH * C * NPIX];

__device__ __forceinline__ uint32_t smem_u32(const void* p) {
    uint32_t a;
    asm("{ .reg .u64 t; cvta.to.shared.u64 t, %1; cvt.u32.u64 %0, t; }" : "=r"(a) : "l"(p));
    return a;
}

// ---------------- weight convert ----------------
__global__ void wconv_kernel(const float* __restrict__ w, const float* __restrict__ g,
                             __half* __restrict__ out, int total) {
    int i = blockIdx.x * 256 + threadIdx.x;
    if (i >= total) return;
    float v = w[i];
    if (g) v *= g[i & (C - 1)];
    out[i] = __float2half_rn(v);
}

// ---------------- fused rmsnorm-scale + transpose -> fp16 ----------------
__global__ __launch_bounds__(256) void normtrans_kernel(const float* __restrict__ x,
                                                        __half* __restrict__ xh) {
    int blk = blockIdx.x;
    int b = blk >> 7;
    int n0 = (blk & 127) << 5;
    int tid = threadIdx.x;
    int w = tid >> 5, j = tid & 31;
    const float* xb = x + (size_t)b * C * NPIX + n0;

    float acc = 0.f;
    for (int c = w; c < C; c += 8) {
        float v = xb[(size_t)c * NPIX + j];
        acc += v * v;
    }
    __shared__ float red[8][32];
    __shared__ float inv[32];
    red[w][j] = acc;
    __syncthreads();
    if (w == 0) {
        float t = 0.f;
        #pragma unroll
        for (int i = 0; i < 8; i++) t += red[i][j];
        inv[j] = SQRT_C / fmaxf(sqrtf(t), 1e-12f);
    }
    __syncthreads();

    __shared__ float ts[64][33];
    for (int c0 = 0; c0 < C; c0 += 64) {
        __syncthreads();
        #pragma unroll
        for (int l = 0; l < 8; l++) {
            int i = l * 256 + tid;
            int cc = i >> 5, nn = i & 31;
            ts[cc][nn] = xb[(size_t)(c0 + cc) * NPIX + nn];
        }
        __syncthreads();
        #pragma unroll
        for (int l = 0; l < 4; l++) {
            int p = l * 256 + tid;
            int nn = p >> 5;
            int cp = p & 31;
            int c = cp * 2;
            float sc = inv[nn];
            __half2 hp;
            hp.x = __float2half_rn(ts[c][nn] * sc);
            hp.y = __float2half_rn(ts[c + 1][nn] * sc);
            *(__half2*)(xh + ((size_t)b * NPIX + n0 + nn) * C + c0 + c) = hp;
        }
    }
}

// ---------------- mma.sync fp16 GEMM, 4-stage, 2 CTA/SM ----------------
__global__ __launch_bounds__(GTHREADS, 2) void hgemm_kernel(
    const __half* __restrict__ A, const __half* __restrict__ B,
    __half* __restrict__ Cout, int M, const float* __restrict__ bias) {
    extern __shared__ __align__(16) char smem[];
    uint32_t sbase = smem_u32(smem);

    int tid = threadIdx.x, wid = tid >> 5, lane = tid & 31;
    int m0 = blockIdx.y * BM, n0 = blockIdx.x * BN, b = blockIdx.z;
    const __half* Bb = B + (size_t)b * NPIX * C;
    __half* Cb = Cout + (size_t)b * M * NPIX;

    int wm = (wid >> 2) * 32;
    int wn = (wid & 3) * 32;

    int rr = tid >> 2, kc = tid & 3;
    uint32_t dstA = (rr * KST + kc * 8) * 2;
    uint32_t dstB = STAGE_BYTES / 2 + dstA;

    float acc[2][4][4];
    #pragma unroll
    for (int i = 0; i < 2; i++)
        #pragma unroll
        for (int j = 0; j < 4; j++)
            #pragma unroll
            for (int q = 0; q < 4; q++) acc[i][j][q] = 0.f;

    auto issue = [&](int ch, int st) {
        if (ch < 16) {
            int k0 = ch << 5;
            uint32_t da = sbase + st * STAGE_BYTES + dstA;
            uint32_t db = sbase + st * STAGE_BYTES + dstB;
            const __half* ga = A + (size_t)(m0 + rr) * C + k0 + kc * 8;
            const __half* gb = Bb + (size_t)(n0 + rr) * C + k0 + kc * 8;
            asm volatile("cp.async.cg.shared.global [%0], [%1], 16;" :: "r"(da), "l"(ga));
            asm volatile("cp.async.cg.shared.global [%0], [%1], 16;" :: "r"(db), "l"(gb));
        }
        asm volatile("cp.async.commit_group;" ::: "memory");
    };

    issue(0, 0);
    issue(1, 1);
    issue(2, 2);

    for (int ch = 0; ch < 16; ch++) {
        asm volatile("cp.async.wait_group 2;" ::: "memory");
        __syncthreads();
        int st = ch % NSTAGE;
        issue(ch + 3, (ch + 3) % NSTAGE);

        uint32_t aBase = sbase + st * STAGE_BYTES;
        uint32_t bBase = aBase + STAGE_BYTES / 2;
        #pragma unroll
        for (int ks = 0; ks < 2; ks++) {
            uint32_t af[2][4], bf[2][4];
            #pragma unroll
            for (int mt = 0; mt < 2; mt++) {
                uint32_t addr = aBase +
                    ((wm + mt * 16 + (lane & 15)) * KST + ks * 16 + (lane >> 4) * 8) * 2;
                asm volatile("ldmatrix.sync.aligned.m8n8.x4.shared.b16 {%0,%1,%2,%3}, [%4];"
                             : "=r"(af[mt][0]), "=r"(af[mt][1]), "=r"(af[mt][2]), "=r"(af[mt][3])
                             : "r"(addr));
            }
            #pragma unroll
            for (int np = 0; np < 2; np++) {
                uint32_t addr = bBase +
                    ((wn + np * 16 + (lane & 15)) * KST + ks * 16 + (lane >> 4) * 8) * 2;
                asm volatile("ldmatrix.sync.aligned.m8n8.x4.shared.b16 {%0,%1,%2,%3}, [%4];"
                             : "=r"(bf[np][0]), "=r"(bf[np][1]), "=r"(bf[np][2]), "=r"(bf[np][3])
                             : "r"(addr));
            }
            #pragma unroll
            for (int mt = 0; mt < 2; mt++) {
                #pragma unroll
                for (int nt = 0; nt < 4; nt++) {
                    uint32_t b0 = bf[nt >> 1][(nt & 1)];
                    uint32_t b1 = bf[nt >> 1][(nt & 1) + 2];
                    asm volatile(
                        "mma.sync.aligned.m16n8k16.row.col.f32.f16.f16.f32 "
                        "{%0,%1,%2,%3}, {%4,%5,%6,%7}, {%8,%9}, {%0,%1,%2,%3};"
                        : "+f"(acc[mt][nt][0]), "+f"(acc[mt][nt][1]),
                          "+f"(acc[mt][nt][2]), "+f"(acc[mt][nt][3])
                        : "r"(af[mt][0]), "r"(af[mt][1]), "r"(af[mt][2]), "r"(af[mt][3]),
                          "r"(b0), "r"(b1));
                }
            }
        }
    }

    #pragma unroll
    for (int mt = 0; mt < 2; mt++) {
        int r = m0 + wm + mt * 16 + (lane >> 2);
        float b0v = bias ? bias[r] : 0.f;
        float b1v = bias ? bias[r + 8] : 0.f;
        #pragma unroll
        for (int nt = 0; nt < 4; nt++) {
            int cn = n0 + wn + nt * 8 + (lane & 3) * 2;
            __half2 h0, h1;
            h0.x = __float2half_rn(acc[mt][nt][0] + b0v);
            h0.y = __float2half_rn(acc[mt][nt][1] + b0v);
            h1.x = __float2half_rn(acc[mt][nt][2] + b1v);
            h1.y = __float2half_rn(acc[mt][nt][3] + b1v);
            *(__half2*)(Cb + (size_t)r * NPIX + cn) = h0;
            *(__half2*)(Cb + (size_t)(r + 8) * NPIX + cn) = h1;
        }
    }
}

// ---------------- kv: exp(k)^T v via mma + inline ksum ----------------
__global__ __launch_bounds__(256) void kv_kernel(const __half* __restrict__ qkvh,
                                                 float* __restrict__ part,
                                                 float* __restrict__ spart) {
    extern __shared__ __align__(16) char ksmem[];
    __half* Ks = (__half*)ksmem;
    __half* Vs = (__half*)(ksmem + 64 * KVPAD * 2);
    int bh = blockIdx.y;
    int b = bh >> 3, h = bh & 7;
    int n0 = blockIdx.x * 256;
    const __half* kb = qkvh + ((size_t)b * QKV_M + 512 + (size_t)h * CH) * NPIX + n0;
    const __half* vb = qkvh + ((size_t)b * QKV_M + 1024 + (size_t)h * CH) * NPIX + n0;
    int tid = threadIdx.x;

    const __half2 l2e = __floats2half2_rn(LOG2E, LOG2E);
    __shared__ float sred[64];
    float kpart[8];
    #pragma unroll
    for (int l = 0; l < 8; l++) {
        int idx = l * 256 + tid;
        int r = idx >> 5;
        int c8 = (idx & 31) * 8;
        uint4 kvv = *(const uint4*)(kb + (size_t)r * NPIX + c8);
        __half2* hp = (__half2*)&kvv;
        float rowsum = 0.f;
        #pragma unroll
        for (int q = 0; q < 4; q++) {
            __half2 t = __hmul2(hp[q], l2e);
            uint32_t rr_;
            asm("ex2.approx.f16x2 %0, %1;" : "=r"(rr_) : "r"(*(uint32_t*)&t));
            hp[q] = *(__half2*)&rr_;
            float2 f = __half22float2(hp[q]);
            rowsum += f.x + f.y;
        }
        kpart[l] = rowsum;
        *(uint4*)(Ks + r * KVPAD + c8) = kvv;
        uint4 vv = *(const uint4*)(vb + (size_t)r * NPIX + c8);
        *(uint4*)(Vs + r * KVPAD + c8) = vv;
    }
    {
        int lane = tid & 31;
        #pragma unroll
        for (int l = 0; l < 8; l++) {
            float s = kpart[l];
            #pragma unroll
            for (int o = 16; o > 0; o >>= 1) s += __shfl_xor_sync(0xffffffffu, s, o);
            if (lane == 0) sred[l * 8 + (tid >> 5)] = s;
        }
    }
    __syncthreads();
    if (tid < 64) {
        spart[((size_t)blockIdx.x * 64 + bh) * CH + tid] = sred[tid];
    }

    int wid = tid >> 5, lane = tid & 31;
    int mc = (wid & 3) * 16, d0 = (wid >> 2) * 32;
    uint32_t sK = smem_u32(Ks), sV = smem_u32(Vs);
    float acc[4][4] = {};
    #pragma unroll
    for (int kk = 0; kk < 16; kk++) {
        uint32_t af[4], bf[2][4];
        uint32_t aaddr = sK + ((mc + (lane & 15)) * KVPAD + kk * 16 + (lane >> 4) * 8) * 2;
        asm volatile("ldmatrix.sync.aligned.m8n8.x4.shared.b16 {%0,%1,%2,%3}, [%4];"
                     : "=r"(af[0]), "=r"(af[1]), "=r"(af[2]), "=r"(af[3]) : "r"(aaddr));
        #pragma unroll
        for (int np = 0; np < 2; np++) {
            uint32_t baddr = sV + ((d0 + np * 16 + (lane & 15)) * KVPAD + kk * 16 + (lane >> 4) * 8) * 2;
            asm volatile("ldmatrix.sync.aligned.m8n8.x4.shared.b16 {%0,%1,%2,%3}, [%4];"
                         : "=r"(bf[np][0]), "=r"(bf[np][1]), "=r"(bf[np][2]), "=r"(bf[np][3])
                         : "r"(baddr));
        }
        #pragma unroll
        for (int nt = 0; nt < 4; nt++) {
            uint32_t b0 = bf[nt >> 1][(nt & 1)];
            uint32_t b1 = bf[nt >> 1][(nt & 1) + 2];
            asm volatile(
                "mma.sync.aligned.m16n8k16.row.col.f32.f16.f16.f32 "
                "{%0,%1,%2,%3}, {%4,%5,%6,%7}, {%8,%9}, {%0,%1,%2,%3};"
                : "+f"(acc[nt][0]), "+f"(acc[nt][1]), "+f"(acc[nt][2]), "+f"(acc[nt][3])
                : "r"(af[0]), "r"(af[1]), "r"(af[2]), "r"(af[3]), "r"(b0), "r"(b1));
        }
    }
    float* pp = part + ((size_t)blockIdx.x * 64 + bh) * (CH * CH);
    int r = mc + (lane >> 2);
    #pragma unroll
    for (int nt = 0; nt < 4; nt++) {
        int d = d0 + nt * 8 + (lane & 3) * 2;
        pp[r * 64 + d] = acc[nt][0];
        pp[r * 64 + d + 1] = acc[nt][1];
        pp[(r + 8) * 64 + d] = acc[nt][2];
        pp[(r + 8) * 64 + d + 1] = acc[nt][3];
    }
}

// ---------------- combine partials -> fp16 attn ----------------
__global__ void attn_finalize(const float* __restrict__ part,
                              const float* __restrict__ spart,
                              __half* __restrict__ attnh) {
    int idx = blockIdx.x * 256 + threadIdx.x;
    int bh = idx >> 12;
    int cd = idx & 4095;
    int c = cd >> 6;
    float s = 0.f, ks = 0.f;
    #pragma unroll
    for (int sp = 0; sp < NSPLIT; sp++) {
        s += part[((size_t)sp * 64 + bh) * 4096 + cd];
        ks += spart[((size_t)sp * 64 + bh) * CH + c];
    }
    attnh[idx] = __float2half_rn(s / ks * 0.125f);
}

// ---------------- qattn via mma ----------------
__global__ __launch_bounds__(256) void qattn_kernel(const __half* __restrict__ qkvh,
                                                    const __half* __restrict__ attnh,
                                                    __half* __restrict__ oh) {
    __shared__ __align__(16) __half qe[128 * 72];
    __shared__ __align__(16) __half att[64 * 72];
    __shared__ float sred[128][2];
    __shared__ float inv[128];
    int bh = blockIdx.y;
    int b = bh >> 3, h = bh & 7;
    int n0 = blockIdx.x * 128;
    int tid = threadIdx.x;

    #pragma unroll
    for (int l = 0; l < 16; l++) {
        int idx = l * 256 + tid;
        int c = idx >> 6, d = idx & 63;
        att[d * 72 + c] = attnh[(size_t)bh * 4096 + idx];
    }
    const __half* qbase = qkvh + ((size_t)b * QKV_M + (size_t)h * CH) * NPIX + n0;
    const __half2 l2e = __floats2half2_rn(LOG2E, LOG2E);
    #pragma unroll
    for (int l = 0; l < 4; l++) {
        int idx = l * 256 + tid;
        int c = idx >> 4;
        int n8 = (idx & 15) * 8;
        uint4 v = *(const uint4*)(qbase + (size_t)c * NPIX + n8);
        __half2* hp = (__half2*)&v;
        #pragma unroll
        for (int q = 0; q < 4; q++) {
            __half2 t = __hmul2(hp[q], l2e);
            uint32_t rr_;
            asm("ex2.approx.f16x2 %0, %1;" : "=r"(rr_) : "r"(*(uint32_t*)&t));
            hp[q] = *(__half2*)&rr_;
        }
        __half* hv = (__half*)&v;
        #pragma unroll
        for (int j = 0; j < 8; j++) qe[(n8 + j) * 72 + c] = hv[j];
    }
    __syncthreads();

    {
        int r = tid >> 1, hf = (tid & 1) * 32;
        float s = 0.f;
        #pragma unroll
        for (int i = 0; i < 16; i++) {
            __half2 h2 = *(__half2*)(qe + r * 72 + hf + i * 2);
            float2 f = __half22float2(h2);
            s += f.x + f.y;
        }
        sred[r][tid & 1] = s;
    }
    __syncthreads();
    if (tid < 128) inv[tid] = 1.0f / (sred[tid][0] + sred[tid][1]);
    __syncthreads();

    int wid = tid >> 5, lane = tid & 31;
    int m0w = (wid >> 1) * 32;
    int d0 = (wid & 1) * 32;
    uint32_t sQ = smem_u32(qe), sA = smem_u32(att);
    float acc[2][4][4];
    #pragma unroll
    for (int i = 0; i < 2; i++)
        #pragma unroll
        for (int j = 0; j < 4; j++)
            #pragma unroll
            for (int q = 0; q < 4; q++) acc[i][j][q] = 0.f;
    #pragma unroll
    for (int kk = 0; kk < 4; kk++) {
        uint32_t af[2][4], bf[2][4];
        #pragma unroll
        for (int mt = 0; mt < 2; mt++) {
            uint32_t addr = sQ + ((m0w + mt * 16 + (lane & 15)) * 72 + kk * 16 + (lane >> 4) * 8) * 2;
            asm volatile("ldmatrix.sync.aligned.m8n8.x4.shared.b16 {%0,%1,%2,%3}, [%4];"
                         : "=r"(af[mt][0]), "=r"(af[mt][1]), "=r"(af[mt][2]), "=r"(af[mt][3])
                         : "r"(addr));
        }
        #pragma unroll
        for (int np = 0; np < 2; np++) {
            uint32_t addr = sA + ((d0 + np * 16 + (lane & 15)) * 72 + kk * 16 + (lane >> 4) * 8) * 2;
            asm volatile("ldmatrix.sync.aligned.m8n8.x4.shared.b16 {%0,%1,%2,%3}, [%4];"
                         : "=r"(bf[np][0]), "=r"(bf[np][1]), "=r"(bf[np][2]), "=r"(bf[np][3])
                         : "r"(addr));
        }
        #pragma unroll
        for (int mt = 0; mt < 2; mt++) {
            #pragma unroll
            for (int nt = 0; nt < 4; nt++) {
                uint32_t b0 = bf[nt >> 1][(nt & 1)];
                uint32_t b1 = bf[nt >> 1][(nt & 1) + 2];
                asm volatile(
                    "mma.sync.aligned.m16n8k16.row.col.f32.f16.f16.f32 "
                    "{%0,%1,%2,%3}, {%4,%5,%6,%7}, {%8,%9}, {%0,%1,%2,%3};"
                    : "+f"(acc[mt][nt][0]), "+f"(acc[mt][nt][1]),
                      "+f"(acc[mt][nt][2]), "+f"(acc[mt][nt][3])
                    : "r"(af[mt][0]), "r"(af[mt][1]), "r"(af[mt][2]), "r"(af[mt][3]),
                      "r"(b0), "r"(b1));
            }
        }
    }

    size_t obase = ((size_t)b * NPIX + n0) * C + (size_t)h * CH;
    #pragma unroll
    for (int mt = 0; mt < 2; mt++) {
        int rn = m0w + mt * 16 + (lane >> 2);
        float i0 = inv[rn], i1 = inv[rn + 8];
        #pragma unroll
        for (int nt = 0; nt < 4; nt++) {
            int d = d0 + nt * 8 + (lane & 3) * 2;
            __half2 h0, h1;
            h0.x = __float2half_rn(acc[mt][nt][0] * i0);
            h0.y = __float2half_rn(acc[mt][nt][1] * i0);
            h1.x = __float2half_rn(acc[mt][nt][2] * i1);
            h1.y = __float2half_rn(acc[mt][nt][3] * i1);
            *(__half2*)(oh + obase + (size_t)rn * C + d) = h0;
            *(__half2*)(oh + obase + (size_t)(rn + 8) * C + d) = h1;
        }
    }
}

// ---------------- final rmsnorm + residual (fp16 t, vectorized) ----------------
__global__ __launch_bounds__(256) void final_kernel(const __half* __restrict__ t,
                                                    const float* __restrict__ x,
                                                    const float* __restrict__ g2,
                                                    float* __restrict__ outp) {
    int blk = blockIdx.x;
    int b = blk >> 6;
    int p0 = (blk & 63) << 6;          // 64 pixels per block, 2 per thread
    int w = threadIdx.x >> 5, j = threadIdx.x & 31;
    const __half* tb = t + (size_t)b * C * NPIX + p0 + j * 2;
    float2 acc = {0.f, 0.f};
    for (int c = w; c < C; c += 8) {
        __half2 h2 = *(const __half2*)(tb + (size_t)c * NPIX);
        float2 f = __half22float2(h2);
        acc.x += f.x * f.x;
        acc.y += f.y * f.y;
    }
    __shared__ float2 red[8][32];
    __shared__ float2 inv[32];
    red[w][j] = acc;
    __syncthreads();
    if (w == 0) {
        float2 s = {0.f, 0.f};
        #pragma unroll
        for (int i = 0; i < 8; i++) {
            s.x += red[i][j].x;
            s.y += red[i][j].y;
        }
        float2 iv;
        iv.x = SQRT_C / fmaxf(sqrtf(s.x), 1e-12f);
        iv.y = SQRT_C / fmaxf(sqrtf(s.y), 1e-12f);
        inv[j] = iv;
    }
    __syncthreads();
    float2 iv = inv[j];
    const float* xb = x + (size_t)b * C * NPIX + p0 + j * 2;
    float* ob = outp + (size_t)b * C * NPIX + p0 + j * 2;
    for (int c = w; c < C; c += 8) {
        __half2 h2 = *(const __half2*)(tb + (size_t)c * NPIX);
        float2 f = __half22float2(h2);
        float2 xv = *(const float2*)(xb + (size_t)c * NPIX);
        float gg = g2[c];
        float2 o;
        o.x = f.x * iv.x * gg + xv.x;
        o.y = f.y * iv.y * gg + xv.y;
        *(float2*)(ob + (size_t)c * NPIX) = o;
    }
}

// ---------------- launch ----------------
extern "C" void kernel_launch(void* const* d_in, const int* in_sizes, int n_in,
                              void* d_out, int out_size) {
    (void)in_sizes; (void)n_in; (void)out_size;
    const float* x      = (const float*)d_in[0];
    const float* norm_g = (const float*)d_in[1];
    const float* qkv_w  = (const float*)d_in[2];
    const float* ffn_w  = (const float*)d_in[3];
    const float* ffn_b  = (const float*)d_in[4];
    const float* ffn_gn = (const float*)d_in[5];
    float* out = (float*)d_out;

    __half *wh, *fh, *xh, *qkvh, *oh, *ffnh, *attnh;
    float *part, *spart;
    cudaGetSymbolAddress((void**)&wh, g_wh);
    cudaGetSymbolAddress((void**)&fh, g_fh);
    cudaGetSymbolAddress((void**)&xh, g_xh);
    cudaGetSymbolAddress((void**)&qkvh, g_qkvh);
    cudaGetSymbolAddress((void**)&part, g_part);
    cudaGetSymbolAddress((void**)&spart, g_spart);
    cudaGetSymbolAddress((void**)&attnh, g_attnh);
    cudaGetSymbolAddress((void**)&oh, g_oh);
    cudaGetSymbolAddress((void**)&ffnh, g_ffnh);

    cudaFuncSetAttribute(hgemm_kernel, cudaFuncAttributeMaxDynamicSharedMemorySize,
                         GEMM_SMEM);
    cudaFuncSetAttribute(kv_kernel, cudaFuncAttributeMaxDynamicSharedMemorySize,
                         KV_SMEM);

    wconv_kernel<<<(QKV_M * C) / 256, 256>>>(qkv_w, norm_g, wh, QKV_M * C);
    wconv_kernel<<<(C * C) / 256, 256>>>(ffn_w, nullptr, fh, C * C);
    normtrans_kernel<<<BATCH * (NPIX / 32), 256>>>(x, xh);
    hgemm_kernel<<<dim3(NPIX / BN, QKV_M / BM, BATCH), GTHREADS, GEMM_SMEM>>>(
        wh, xh, qkvh, QKV_M, nullptr);
    kv_kernel<<<dim3(NSPLIT, BATCH * HEADS), 256, KV_SMEM>>>(qkvh, part, spart);
    attn_finalize<<<(BATCH * HEADS * CH * CH) / 256, 256>>>(part, spart, attnh);
    qattn_kernel<<<dim3(NPIX / 128, BATCH * HEADS), 256>>>(qkvh, attnh, oh);
    hgemm_kernel<<<dim3(NPIX / BN, C / BM, BATCH), GTHREADS, GEMM_SMEM>>>(
        fh, oh, ffnh, C, ffn_b);
    final_kernel<<<BATCH * (NPIX / 64), 256>>>(ffnh, x, ffn_gn, out);
}

// round 17
// speedup vs baseline: 1.4661x; 1.4661x over previous
#include <cuda_runtime.h>
#include <cuda_bf16.h>
#include <cuda_fp16.h>
#include <math.h>
#include <stdint.h>

#define BATCH 8
#define C 512
#define NPIX 4096
#define HEADS 8
#define CH 64
#define QKV_M 1536
#define NSPLIT 16
#define SQRT_C 22.627416997969522f
#define LOG2E 1.4426950408889634f

// GEMM tiling (R15 frozen): CTA 128x128, BK=32, 512 threads, warp 32x32, 2 CTA/SM, 3 stages
#define BM 128
#define BN 128
#define KST 40
#define GTHREADS 512
#define STAGE_BYTES (2 * BM * KST * 2)
#define GEMM_SMEM (3 * STAGE_BYTES)

#define KVPAD 264
#define KV_SMEM (2 * 64 * KVPAD * 2)

// ---------------- device scratch ----------------
__device__ __half g_wh[QKV_M * C];
__device__ __half g_fh[C * C];
__device__ __half g_xh[(size_t)BATCH * NPIX * C];
__device__ __half g_qkvh[(size_t)BATCH * QKV_M * NPIX];
__device__ float g_part[(size_t)NSPLIT * BATCH * HEADS * CH * CH];
__device__ float g_spart[(size_t)NSPLIT * BATCH * HEADS * CH];
__device__ __half g_attnh[BATCH * HEADS * CH * CH];
__device__ __half g_oh[(size_t)BATCH * NPIX * C];
__device__ __half g_ffnh[(size_t)BATCH * C * NPIX];

__device__ __forceinline__ uint32_t smem_u32(const void* p) {
    uint32_t a;
    asm("{ .reg .u64 t; cvta.to.shared.u64 t, %1; cvt.u32.u64 %0, t; }" : "=r"(a) : "l"(p));
    return a;
}

// ---------------- weight convert ----------------
__global__ void wconv_kernel(const float* __restrict__ w, const float* __restrict__ g,
                             __half* __restrict__ out, int total) {
    int i = blockIdx.x * 256 + threadIdx.x;
    if (i >= total) return;
    float v = w[i];
    if (g) v *= g[i & (C - 1)];
    out[i] = __float2half_rn(v);
}

// ---------------- fused rmsnorm-scale + transpose -> fp16 ----------------
__global__ __launch_bounds__(256) void normtrans_kernel(const float* __restrict__ x,
                                                        __half* __restrict__ xh) {
    int blk = blockIdx.x;
    int b = blk >> 7;
    int n0 = (blk & 127) << 5;
    int tid = threadIdx.x;
    int w = tid >> 5, j = tid & 31;
    const float* xb = x + (size_t)b * C * NPIX + n0;

    float acc = 0.f;
    for (int c = w; c < C; c += 8) {
        float v = xb[(size_t)c * NPIX + j];
        acc += v * v;
    }
    __shared__ float red[8][32];
    __shared__ float inv[32];
    red[w][j] = acc;
    __syncthreads();
    if (w == 0) {
        float t = 0.f;
        #pragma unroll
        for (int i = 0; i < 8; i++) t += red[i][j];
        inv[j] = SQRT_C / fmaxf(sqrtf(t), 1e-12f);
    }
    __syncthreads();

    __shared__ float ts[64][33];
    for (int c0 = 0; c0 < C; c0 += 64) {
        __syncthreads();
        #pragma unroll
        for (int l = 0; l < 8; l++) {
            int i = l * 256 + tid;
            int cc = i >> 5, nn = i & 31;
            ts[cc][nn] = xb[(size_t)(c0 + cc) * NPIX + nn];
        }
        __syncthreads();
        #pragma unroll
        for (int l = 0; l < 4; l++) {
            int p = l * 256 + tid;
            int nn = p >> 5;
            int cp = p & 31;
            int c = cp * 2;
            float sc = inv[nn];
            __half2 hp;
            hp.x = __float2half_rn(ts[c][nn] * sc);
            hp.y = __float2half_rn(ts[c + 1][nn] * sc);
            *(__half2*)(xh + ((size_t)b * NPIX + n0 + nn) * C + c0 + c) = hp;
        }
    }
}

// ---------------- mma.sync fp16 GEMM (R15 frozen: 3-stage, wait 1) ----------------
__global__ __launch_bounds__(GTHREADS, 2) void hgemm_kernel(
    const __half* __restrict__ A, const __half* __restrict__ B,
    __half* __restrict__ Cout, int M, const float* __restrict__ bias) {
    extern __shared__ __align__(16) char smem[];
    uint32_t sbase = smem_u32(smem);

    int tid = threadIdx.x, wid = tid >> 5, lane = tid & 31;
    int m0 = blockIdx.y * BM, n0 = blockIdx.x * BN, b = blockIdx.z;
    const __half* Bb = B + (size_t)b * NPIX * C;
    __half* Cb = Cout + (size_t)b * M * NPIX;

    int wm = (wid >> 2) * 32;
    int wn = (wid & 3) * 32;

    int rr = tid >> 2, kc = tid & 3;
    uint32_t dstA = (rr * KST + kc * 8) * 2;
    uint32_t dstB = STAGE_BYTES / 2 + dstA;

    float acc[2][4][4];
    #pragma unroll
    for (int i = 0; i < 2; i++)
        #pragma unroll
        for (int j = 0; j < 4; j++)
            #pragma unroll
            for (int q = 0; q < 4; q++) acc[i][j][q] = 0.f;

    auto issue = [&](int ch, int st) {
        if (ch < 16) {
            int k0 = ch << 5;
            uint32_t da = sbase + st * STAGE_BYTES + dstA;
            uint32_t db = sbase + st * STAGE_BYTES + dstB;
            const __half* ga = A + (size_t)(m0 + rr) * C + k0 + kc * 8;
            const __half* gb = Bb + (size_t)(n0 + rr) * C + k0 + kc * 8;
            asm volatile("cp.async.cg.shared.global [%0], [%1], 16;" :: "r"(da), "l"(ga));
            asm volatile("cp.async.cg.shared.global [%0], [%1], 16;" :: "r"(db), "l"(gb));
        }
        asm volatile("cp.async.commit_group;" ::: "memory");
    };

    issue(0, 0);
    issue(1, 1);

    for (int ch = 0; ch < 16; ch++) {
        asm volatile("cp.async.wait_group 1;" ::: "memory");
        __syncthreads();
        int st = ch % 3;
        issue(ch + 2, (ch + 2) % 3);

        uint32_t aBase = sbase + st * STAGE_BYTES;
        uint32_t bBase = aBase + STAGE_BYTES / 2;
        #pragma unroll
        for (int ks = 0; ks < 2; ks++) {
            uint32_t af[2][4], bf[2][4];
            #pragma unroll
            for (int mt = 0; mt < 2; mt++) {
                uint32_t addr = aBase +
                    ((wm + mt * 16 + (lane & 15)) * KST + ks * 16 + (lane >> 4) * 8) * 2;
                asm volatile("ldmatrix.sync.aligned.m8n8.x4.shared.b16 {%0,%1,%2,%3}, [%4];"
                             : "=r"(af[mt][0]), "=r"(af[mt][1]), "=r"(af[mt][2]), "=r"(af[mt][3])
                             : "r"(addr));
            }
            #pragma unroll
            for (int np = 0; np < 2; np++) {
                uint32_t addr = bBase +
                    ((wn + np * 16 + (lane & 15)) * KST + ks * 16 + (lane >> 4) * 8) * 2;
                asm volatile("ldmatrix.sync.aligned.m8n8.x4.shared.b16 {%0,%1,%2,%3}, [%4];"
                             : "=r"(bf[np][0]), "=r"(bf[np][1]), "=r"(bf[np][2]), "=r"(bf[np][3])
                             : "r"(addr));
            }
            #pragma unroll
            for (int mt = 0; mt < 2; mt++) {
                #pragma unroll
                for (int nt = 0; nt < 4; nt++) {
                    uint32_t b0 = bf[nt >> 1][(nt & 1)];
                    uint32_t b1 = bf[nt >> 1][(nt & 1) + 2];
                    asm volatile(
                        "mma.sync.aligned.m16n8k16.row.col.f32.f16.f16.f32 "
                        "{%0,%1,%2,%3}, {%4,%5,%6,%7}, {%8,%9}, {%0,%1,%2,%3};"
                        : "+f"(acc[mt][nt][0]), "+f"(acc[mt][nt][1]),
                          "+f"(acc[mt][nt][2]), "+f"(acc[mt][nt][3])
                        : "r"(af[mt][0]), "r"(af[mt][1]), "r"(af[mt][2]), "r"(af[mt][3]),
                          "r"(b0), "r"(b1));
                }
            }
        }
    }

    #pragma unroll
    for (int mt = 0; mt < 2; mt++) {
        int r = m0 + wm + mt * 16 + (lane >> 2);
        float b0v = bias ? bias[r] : 0.f;
        float b1v = bias ? bias[r + 8] : 0.f;
        #pragma unroll
        for (int nt = 0; nt < 4; nt++) {
            int cn = n0 + wn + nt * 8 + (lane & 3) * 2;
            __half2 h0, h1;
            h0.x = __float2half_rn(acc[mt][nt][0] + b0v);
            h0.y = __float2half_rn(acc[mt][nt][1] + b0v);
            h1.x = __float2half_rn(acc[mt][nt][2] + b1v);
            h1.y = __float2half_rn(acc[mt][nt][3] + b1v);
            *(__half2*)(Cb + (size_t)r * NPIX + cn) = h0;
            *(__half2*)(Cb + (size_t)(r + 8) * NPIX + cn) = h1;
        }
    }
}

// ---------------- kv: exp(k)^T v via mma + inline ksum ----------------
__global__ __launch_bounds__(256) void kv_kernel(const __half* __restrict__ qkvh,
                                                 float* __restrict__ part,
                                                 float* __restrict__ spart) {
    extern __shared__ __align__(16) char ksmem[];
    __half* Ks = (__half*)ksmem;
    __half* Vs = (__half*)(ksmem + 64 * KVPAD * 2);
    int bh = blockIdx.y;
    int b = bh >> 3, h = bh & 7;
    int n0 = blockIdx.x * 256;
    const __half* kb = qkvh + ((size_t)b * QKV_M + 512 + (size_t)h * CH) * NPIX + n0;
    const __half* vb = qkvh + ((size_t)b * QKV_M + 1024 + (size_t)h * CH) * NPIX + n0;
    int tid = threadIdx.x;

    const __half2 l2e = __floats2half2_rn(LOG2E, LOG2E);
    __shared__ float sred[64];
    float kpart[8];
    #pragma unroll
    for (int l = 0; l < 8; l++) {
        int idx = l * 256 + tid;
        int r = idx >> 5;
        int c8 = (idx & 31) * 8;
        uint4 kvv = *(const uint4*)(kb + (size_t)r * NPIX + c8);
        __half2* hp = (__half2*)&kvv;
        float rowsum = 0.f;
        #pragma unroll
        for (int q = 0; q < 4; q++) {
            __half2 t = __hmul2(hp[q], l2e);
            uint32_t rr_;
            asm("ex2.approx.f16x2 %0, %1;" : "=r"(rr_) : "r"(*(uint32_t*)&t));
            hp[q] = *(__half2*)&rr_;
            float2 f = __half22float2(hp[q]);
            rowsum += f.x + f.y;
        }
        kpart[l] = rowsum;
        *(uint4*)(Ks + r * KVPAD + c8) = kvv;
        uint4 vv = *(const uint4*)(vb + (size_t)r * NPIX + c8);
        *(uint4*)(Vs + r * KVPAD + c8) = vv;
    }
    {
        int lane = tid & 31;
        #pragma unroll
        for (int l = 0; l < 8; l++) {
            float s = kpart[l];
            #pragma unroll
            for (int o = 16; o > 0; o >>= 1) s += __shfl_xor_sync(0xffffffffu, s, o);
            if (lane == 0) sred[l * 8 + (tid >> 5)] = s;
        }
    }
    __syncthreads();
    if (tid < 64) {
        spart[((size_t)blockIdx.x * 64 + bh) * CH + tid] = sred[tid];
    }

    int wid = tid >> 5, lane = tid & 31;
    int mc = (wid & 3) * 16, d0 = (wid >> 2) * 32;
    uint32_t sK = smem_u32(Ks), sV = smem_u32(Vs);
    float acc[4][4] = {};
    #pragma unroll
    for (int kk = 0; kk < 16; kk++) {
        uint32_t af[4], bf[2][4];
        uint32_t aaddr = sK + ((mc + (lane & 15)) * KVPAD + kk * 16 + (lane >> 4) * 8) * 2;
        asm volatile("ldmatrix.sync.aligned.m8n8.x4.shared.b16 {%0,%1,%2,%3}, [%4];"
                     : "=r"(af[0]), "=r"(af[1]), "=r"(af[2]), "=r"(af[3]) : "r"(aaddr));
        #pragma unroll
        for (int np = 0; np < 2; np++) {
            uint32_t baddr = sV + ((d0 + np * 16 + (lane & 15)) * KVPAD + kk * 16 + (lane >> 4) * 8) * 2;
            asm volatile("ldmatrix.sync.aligned.m8n8.x4.shared.b16 {%0,%1,%2,%3}, [%4];"
                         : "=r"(bf[np][0]), "=r"(bf[np][1]), "=r"(bf[np][2]), "=r"(bf[np][3])
                         : "r"(baddr));
        }
        #pragma unroll
        for (int nt = 0; nt < 4; nt++) {
            uint32_t b0 = bf[nt >> 1][(nt & 1)];
            uint32_t b1 = bf[nt >> 1][(nt & 1) + 2];
            asm volatile(
                "mma.sync.aligned.m16n8k16.row.col.f32.f16.f16.f32 "
                "{%0,%1,%2,%3}, {%4,%5,%6,%7}, {%8,%9}, {%0,%1,%2,%3};"
                : "+f"(acc[nt][0]), "+f"(acc[nt][1]), "+f"(acc[nt][2]), "+f"(acc[nt][3])
                : "r"(af[0]), "r"(af[1]), "r"(af[2]), "r"(af[3]), "r"(b0), "r"(b1));
        }
    }
    float* pp = part + ((size_t)blockIdx.x * 64 + bh) * (CH * CH);
    int r = mc + (lane >> 2);
    #pragma unroll
    for (int nt = 0; nt < 4; nt++) {
        int d = d0 + nt * 8 + (lane & 3) * 2;
        pp[r * 64 + d] = acc[nt][0];
        pp[r * 64 + d + 1] = acc[nt][1];
        pp[(r + 8) * 64 + d] = acc[nt][2];
        pp[(r + 8) * 64 + d + 1] = acc[nt][3];
    }
}

// ---------------- combine partials -> fp16 attn ----------------
__global__ void attn_finalize(const float* __restrict__ part,
                              const float* __restrict__ spart,
                              __half* __restrict__ attnh) {
    int idx = blockIdx.x * 256 + threadIdx.x;
    int bh = idx >> 12;
    int cd = idx & 4095;
    int c = cd >> 6;
    float s = 0.f, ks = 0.f;
    #pragma unroll
    for (int sp = 0; sp < NSPLIT; sp++) {
        s += part[((size_t)sp * 64 + bh) * 4096 + cd];
        ks += spart[((size_t)sp * 64 + bh) * CH + c];
    }
    attnh[idx] = __float2half_rn(s / ks * 0.125f);
}

// ---------------- qattn via mma ----------------
__global__ __launch_bounds__(256) void qattn_kernel(const __half* __restrict__ qkvh,
                                                    const __half* __restrict__ attnh,
                                                    __half* __restrict__ oh) {
    __shared__ __align__(16) __half qe[128 * 72];
    __shared__ __align__(16) __half att[64 * 72];
    __shared__ float sred[128][2];
    __shared__ float inv[128];
    int bh = blockIdx.y;
    int b = bh >> 3, h = bh & 7;
    int n0 = blockIdx.x * 128;
    int tid = threadIdx.x;

    #pragma unroll
    for (int l = 0; l < 16; l++) {
        int idx = l * 256 + tid;
        int c = idx >> 6, d = idx & 63;
        att[d * 72 + c] = attnh[(size_t)bh * 4096 + idx];
    }
    const __half* qbase = qkvh + ((size_t)b * QKV_M + (size_t)h * CH) * NPIX + n0;
    const __half2 l2e = __floats2half2_rn(LOG2E, LOG2E);
    #pragma unroll
    for (int l = 0; l < 4; l++) {
        int idx = l * 256 + tid;
        int c = idx >> 4;
        int n8 = (idx & 15) * 8;
        uint4 v = *(const uint4*)(qbase + (size_t)c * NPIX + n8);
        __half2* hp = (__half2*)&v;
        #pragma unroll
        for (int q = 0; q < 4; q++) {
            __half2 t = __hmul2(hp[q], l2e);
            uint32_t rr_;
            asm("ex2.approx.f16x2 %0, %1;" : "=r"(rr_) : "r"(*(uint32_t*)&t));
            hp[q] = *(__half2*)&rr_;
        }
        __half* hv = (__half*)&v;
        #pragma unroll
        for (int j = 0; j < 8; j++) qe[(n8 + j) * 72 + c] = hv[j];
    }
    __syncthreads();

    {
        int r = tid >> 1, hf = (tid & 1) * 32;
        float s = 0.f;
        #pragma unroll
        for (int i = 0; i < 16; i++) {
            __half2 h2 = *(__half2*)(qe + r * 72 + hf + i * 2);
            float2 f = __half22float2(h2);
            s += f.x + f.y;
        }
        sred[r][tid & 1] = s;
    }
    __syncthreads();
    if (tid < 128) inv[tid] = 1.0f / (sred[tid][0] + sred[tid][1]);
    __syncthreads();

    int wid = tid >> 5, lane = tid & 31;
    int m0w = (wid >> 1) * 32;
    int d0 = (wid & 1) * 32;
    uint32_t sQ = smem_u32(qe), sA = smem_u32(att);
    float acc[2][4][4];
    #pragma unroll
    for (int i = 0; i < 2; i++)
        #pragma unroll
        for (int j = 0; j < 4; j++)
            #pragma unroll
            for (int q = 0; q < 4; q++) acc[i][j][q] = 0.f;
    #pragma unroll
    for (int kk = 0; kk < 4; kk++) {
        uint32_t af[2][4], bf[2][4];
        #pragma unroll
        for (int mt = 0; mt < 2; mt++) {
            uint32_t addr = sQ + ((m0w + mt * 16 + (lane & 15)) * 72 + kk * 16 + (lane >> 4) * 8) * 2;
            asm volatile("ldmatrix.sync.aligned.m8n8.x4.shared.b16 {%0,%1,%2,%3}, [%4];"
                         : "=r"(af[mt][0]), "=r"(af[mt][1]), "=r"(af[mt][2]), "=r"(af[mt][3])
                         : "r"(addr));
        }
        #pragma unroll
        for (int np = 0; np < 2; np++) {
            uint32_t addr = sA + ((d0 + np * 16 + (lane & 15)) * 72 + kk * 16 + (lane >> 4) * 8) * 2;
            asm volatile("ldmatrix.sync.aligned.m8n8.x4.shared.b16 {%0,%1,%2,%3}, [%4];"
                         : "=r"(bf[np][0]), "=r"(bf[np][1]), "=r"(bf[np][2]), "=r"(bf[np][3])
                         : "r"(addr));
        }
        #pragma unroll
        for (int mt = 0; mt < 2; mt++) {
            #pragma unroll
            for (int nt = 0; nt < 4; nt++) {
                uint32_t b0 = bf[nt >> 1][(nt & 1)];
                uint32_t b1 = bf[nt >> 1][(nt & 1) + 2];
                asm volatile(
                    "mma.sync.aligned.m16n8k16.row.col.f32.f16.f16.f32 "
                    "{%0,%1,%2,%3}, {%4,%5,%6,%7}, {%8,%9}, {%0,%1,%2,%3};"
                    : "+f"(acc[mt][nt][0]), "+f"(acc[mt][nt][1]),
                      "+f"(acc[mt][nt][2]), "+f"(acc[mt][nt][3])
                    : "r"(af[mt][0]), "r"(af[mt][1]), "r"(af[mt][2]), "r"(af[mt][3]),
                      "r"(b0), "r"(b1));
            }
        }
    }

    size_t obase = ((size_t)b * NPIX + n0) * C + (size_t)h * CH;
    #pragma unroll
    for (int mt = 0; mt < 2; mt++) {
        int rn = m0w + mt * 16 + (lane >> 2);
        float i0 = inv[rn], i1 = inv[rn + 8];
        #pragma unroll
        for (int nt = 0; nt < 4; nt++) {
            int d = d0 + nt * 8 + (lane & 3) * 2;
            __half2 h0, h1;
            h0.x = __float2half_rn(acc[mt][nt][0] * i0);
            h0.y = __float2half_rn(acc[mt][nt][1] * i0);
            h1.x = __float2half_rn(acc[mt][nt][2] * i1);
            h1.y = __float2half_rn(acc[mt][nt][3] * i1);
            *(__half2*)(oh + obase + (size_t)rn * C + d) = h0;
            *(__half2*)(oh + obase + (size_t)(rn + 8) * C + d) = h1;
        }
    }
}

// ---------------- final rmsnorm + residual (fp16 t, vectorized) ----------------
__global__ __launch_bounds__(256) void final_kernel(const __half* __restrict__ t,
                                                    const float* __restrict__ x,
                                                    const float* __restrict__ g2,
                                                    float* __restrict__ outp) {
    int blk = blockIdx.x;
    int b = blk >> 6;
    int p0 = (blk & 63) << 6;
    int w = threadIdx.x >> 5, j = threadIdx.x & 31;
    const __half* tb = t + (size_t)b * C * NPIX + p0 + j * 2;
    float2 acc = {0.f, 0.f};
    for (int c = w; c < C; c += 8) {
        __half2 h2 = *(const __half2*)(tb + (size_t)c * NPIX);
        float2 f = __half22float2(h2);
        acc.x += f.x * f.x;
        acc.y += f.y * f.y;
    }
    __shared__ float2 red[8][32];
    __shared__ float2 inv[32];
    red[w][j] = acc;
    __syncthreads();
    if (w == 0) {
        float2 s = {0.f, 0.f};
        #pragma unroll
        for (int i = 0; i < 8; i++) {
            s.x += red[i][j].x;
            s.y += red[i][j].y;
        }
        float2 iv;
        iv.x = SQRT_C / fmaxf(sqrtf(s.x), 1e-12f);
        iv.y = SQRT_C / fmaxf(sqrtf(s.y), 1e-12f);
        inv[j] = iv;
    }
    __syncthreads();
    float2 iv = inv[j];
    const float* xb = x + (size_t)b * C * NPIX + p0 + j * 2;
    float* ob = outp + (size_t)b * C * NPIX + p0 + j * 2;
    for (int c = w; c < C; c += 8) {
        __half2 h2 = *(const __half2*)(tb + (size_t)c * NPIX);
        float2 f = __half22float2(h2);
        float2 xv = *(const float2*)(xb + (size_t)c * NPIX);
        float gg = g2[c];
        float2 o;
        o.x = f.x * iv.x * gg + xv.x;
        o.y = f.y * iv.y * gg + xv.y;
        *(float2*)(ob + (size_t)c * NPIX) = o;
    }
}

// ---------------- launch ----------------
extern "C" void kernel_launch(void* const* d_in, const int* in_sizes, int n_in,
                              void* d_out, int out_size) {
    (void)in_sizes; (void)n_in; (void)out_size;
    const float* x      = (const float*)d_in[0];
    const float* norm_g = (const float*)d_in[1];
    const float* qkv_w  = (const float*)d_in[2];
    const float* ffn_w  = (const float*)d_in[3];
    const float* ffn_b  = (const float*)d_in[4];
    const float* ffn_gn = (const float*)d_in[5];
    float* out = (float*)d_out;

    __half *wh, *fh, *xh, *qkvh, *oh, *ffnh, *attnh;
    float *part, *spart;
    cudaGetSymbolAddress((void**)&wh, g_wh);
    cudaGetSymbolAddress((void**)&fh, g_fh);
    cudaGetSymbolAddress((void**)&xh, g_xh);
    cudaGetSymbolAddress((void**)&qkvh, g_qkvh);
    cudaGetSymbolAddress((void**)&part, g_part);
    cudaGetSymbolAddress((void**)&spart, g_spart);
    cudaGetSymbolAddress((void**)&attnh, g_attnh);
    cudaGetSymbolAddress((void**)&oh, g_oh);
    cudaGetSymbolAddress((void**)&ffnh, g_ffnh);

    cudaFuncSetAttribute(hgemm_kernel, cudaFuncAttributeMaxDynamicSharedMemorySize,
                         GEMM_SMEM);
    cudaFuncSetAttribute(kv_kernel, cudaFuncAttributeMaxDynamicSharedMemorySize,
                         KV_SMEM);

    wconv_kernel<<<(QKV_M * C) / 256, 256>>>(qkv_w, norm_g, wh, QKV_M * C);
    wconv_kernel<<<(C * C) / 256, 256>>>(ffn_w, nullptr, fh, C * C);
    normtrans_kernel<<<BATCH * (NPIX / 32), 256>>>(x, xh);
    hgemm_kernel<<<dim3(NPIX / BN, QKV_M / BM, BATCH), GTHREADS, GEMM_SMEM>>>(
        wh, xh, qkvh, QKV_M, nullptr);
    kv_kernel<<<dim3(NSPLIT, BATCH * HEADS), 256, KV_SMEM>>>(qkvh, part, spart);
    attn_finalize<<<(BATCH * HEADS * CH * CH) / 256, 256>>>(part, spart, attnh);
    qattn_kernel<<<dim3(NPIX / 128, BATCH * HEADS), 256>>>(qkvh, attnh, oh);
    hgemm_kernel<<<dim3(NPIX / BN, C / BM, BATCH), GTHREADS, GEMM_SMEM>>>(
        fh, oh, ffnh, C, ffn_b);
    final_kernel<<<BATCH * (NPIX / 64), 256>>>(ffnh, x, ffn_gn, out);
}